// round 10
// baseline (speedup 1.0000x reference)
#include <cuda_runtime.h>
#include <cuda_fp16.h>
#include <mma.h>
#include <stdint.h>

using namespace nvcuda;

#define KK 128
#define BATCH 256
#define DD 1024
#define BK (BATCH*KK)
#define LDA 136           // halves per A/W smem row (272 B)
#define LDS 132           // floats per S smem row
#define WTILE 34816       // one W tile in smem

// static scratch (allocation-free rule)
__device__ float  g_buf0[512 * BATCH * KK];
__device__ float  g_buf1[256 * BATCH * KK];
__device__ __half g_wh[1023 * KK * KK];      // softmax(W) fp16

// ---- pair-kernel smem layout (R7) ----
#define SM_W0   0
#define SM_W1   34816
#define SM_A    69632
#define SM_S0   78336
#define SM_MSUM 95232
#define SMEM_BYTES (SM_MSUM + 192)

// ---- pair_fast smem layout (3 W slots) ----
#define PF_W0   0
#define PF_W1   34816
#define PF_W2   69632
#define PF_A    104448
#define PF_S0   113152
#define PF_MSUM 130048
#define PF_BYTES (PF_MSUM + 192)

// ---- tail smem layout (5 W slots + A0/A1/S0) ----
#define TL_A0   174080
#define TL_A1   182784
#define TL_S0   191488
#define TL_MSUM 208384
#define TL_BYTES (TL_MSUM + 192)

// ---------------- helpers ----------------
static __device__ __forceinline__ uint32_t smem_u32(const void* p) {
    uint32_t a;
    asm("{ .reg .u64 t; cvta.to.shared.u64 t, %1; cvt.u32.u64 %0, t; }" : "=r"(a) : "l"(p));
    return a;
}
static __device__ __forceinline__ void cp_async16(uint32_t dst, const void* src) {
    asm volatile("cp.async.cg.shared.global [%0], [%1], 16;" :: "r"(dst), "l"(src));
}
static __device__ __forceinline__ void cp_commit() {
    asm volatile("cp.async.commit_group;" ::: "memory");
}
template<int N> static __device__ __forceinline__ void cp_wait() {
    asm volatile("cp.async.wait_group %0;" :: "n"(N) : "memory");
}
static __device__ __forceinline__ float warp_max(float m) {
    #pragma unroll
    for (int o = 16; o; o >>= 1) m = fmaxf(m, __shfl_xor_sync(0xffffffffu, m, o));
    return m;
}
static __device__ __forceinline__ float max4(float4 v) {
    return fmaxf(fmaxf(v.x, v.y), fmaxf(v.z, v.w));
}

// ---------------- K0: softmax(W) -> fp16, all nodes ----------------
__global__ void __launch_bounds__(256) softmax_w_kernel(const float* __restrict__ w) {
    const int node = blockIdx.x;
    const int wid = threadIdx.x >> 5, lane = threadIdx.x & 31;
    const float* wn = w + (size_t)node * (KK * KK);
    __half* out = g_wh + (size_t)node * (KK * KK);
    for (int i = wid; i < KK; i += 8) {
        float4 v = ((const float4*)(wn + i * KK))[lane];
        float m = warp_max(max4(v));
        float e0 = __expf(v.x - m), e1 = __expf(v.y - m);
        float e2 = __expf(v.z - m), e3 = __expf(v.w - m);
        float s = e0 + e1 + e2 + e3;
        #pragma unroll
        for (int o = 16; o; o >>= 1) s += __shfl_xor_sync(0xffffffffu, s, o);
        float inv = 1.0f / s;
        __half2 h0 = __floats2half2_rn(e0 * inv, e1 * inv);
        __half2 h1 = __floats2half2_rn(e2 * inv, e3 * inv);
        uint2 pk; pk.x = *(uint32_t*)&h0; pk.y = *(uint32_t*)&h1;
        *(uint2*)&out[i * KK + 4 * lane] = pk;
    }
}

// in-register 32x128x128 GEMM: acc[m,i] = sum_j A[m,j]*W[i,j]; warp tile 16m x 32n
using AccFrag = wmma::fragment<wmma::accumulator, 16, 16, 16, float>;
static __device__ __forceinline__ void gemm32_acc(const __half* As, const __half* Wh,
                                                  AccFrag acc[2], int wid) {
    const int warp_m = wid & 1, warp_n = wid >> 1;
    const int m_base = warp_m * 16, n_base = warp_n * 32;
    wmma::fill_fragment(acc[0], 0.0f);
    wmma::fill_fragment(acc[1], 0.0f);
    #pragma unroll
    for (int k = 0; k < 8; k++) {
        wmma::fragment<wmma::matrix_a, 16, 16, 16, __half, wmma::row_major> af;
        wmma::load_matrix_sync(af, &As[m_base * LDA + 16 * k], LDA);
        #pragma unroll
        for (int j = 0; j < 2; j++) {
            wmma::fragment<wmma::matrix_b, 16, 16, 16, __half, wmma::col_major> bf;
            wmma::load_matrix_sync(bf, &Wh[(n_base + 16 * j) * LDA + 16 * k], LDA);
            wmma::mma_sync(acc[j], af, bf, acc[j]);
        }
    }
}
static __device__ __forceinline__ void store_acc(AccFrag acc[2], float* Out, int wid) {
    const int warp_m = wid & 1, warp_n = wid >> 1;
    #pragma unroll
    for (int j = 0; j < 2; j++)
        wmma::store_matrix_sync(&Out[(warp_m * 16) * LDS + warp_n * 32 + 16 * j],
                                acc[j], LDS, wmma::mem_row_major);
}
static __device__ __forceinline__ void cp_wtile(uint32_t dst, const __half* wsrc, int tid) {
    const char* ws = (const char*)wsrc;
    #pragma unroll
    for (int c = tid; c < 2048; c += 256)
        cp_async16(dst + (c >> 4) * 272 + (c & 15) * 16, ws + (c >> 4) * 256 + (c & 15) * 16);
    cp_commit();
}

// shared stage helpers --------------------------------------------------
static __device__ __forceinline__ void build_A_row(
    __half* dst, float* Msum, int r, int lane, float4 v, bool setM, float addM)
{
    float m = warp_max(max4(v));
    __half2 h0 = __floats2half2_rn(__expf(v.x - m), __expf(v.y - m));
    __half2 h1 = __floats2half2_rn(__expf(v.z - m), __expf(v.w - m));
    uint2 pk; pk.x = *(uint32_t*)&h0; pk.y = *(uint32_t*)&h1;
    *(uint2*)&dst[r * LDA + 4 * lane] = pk;
    if (setM && lane == 0) Msum[r] = m + addM;
}

// ---------------- fused level-pair kernel (R7, verbatim flow) ----------------
template<bool LEAF>
__global__ void __launch_bounds__(256, 2) pair_kernel(
    int insel, int outsel, int wlo, int wup,
    const float* __restrict__ x, const float* __restrict__ mu,
    const float* __restrict__ ls, float* __restrict__ dout)
{
    extern __shared__ char smem[];
    __half* As = (__half*)(smem + SM_A);
    float* S0  = (float*)(smem + SM_S0);
    float* Pm  = (float*)(smem + SM_S0);
    float* Msum = (float*)(smem + SM_MSUM);
    const uint32_t sb = smem_u32(smem);

    const int tid = threadIdx.x, wid = tid >> 5, lane = tid & 31;
    const int node = blockIdx.y;
    const int b0 = blockIdx.x * 32;

    const float* yin = (insel == 0) ? g_buf0 : g_buf1;
    float* yout = (outsel == 0) ? g_buf0 : ((outsel == 1) ? g_buf1 : dout);

    cp_wtile(sb + SM_W0, g_wh + (size_t)(wlo + 2 * node) * (KK * KK), tid);
    cp_wtile(sb + SM_W1, g_wh + (size_t)(wlo + 2 * node + 1) * (KK * KK), tid);

    if (LEAF) {
        if (tid < 128) {
            int v0 = 4 * node, v1 = 4 * node + 1, v2 = 4 * node + 2, v3 = 4 * node + 3;
            float l0 = ls[v0 * KK + tid], l1 = ls[v1 * KK + tid];
            float l2 = ls[v2 * KK + tid], l3 = ls[v3 * KK + tid];
            Pm[0 * 128 + tid] = mu[v0 * KK + tid];
            Pm[1 * 128 + tid] = __expf(-l0);
            Pm[2 * 128 + tid] = mu[v1 * KK + tid];
            Pm[3 * 128 + tid] = __expf(-l1);
            Pm[4 * 128 + tid] = -l0 - l1 - 1.8378770664093453f;
            Pm[5 * 128 + tid] = mu[v2 * KK + tid];
            Pm[6 * 128 + tid] = __expf(-l2);
            Pm[7 * 128 + tid] = mu[v3 * KK + tid];
            Pm[8 * 128 + tid] = __expf(-l3);
            Pm[9 * 128 + tid] = -l2 - l3 - 1.8378770664093453f;
        }
        __syncthreads();
    }

    float4 v1r[4];
    float m0r[4], m1r[4];
    #pragma unroll
    for (int it = 0; it < 4; it++) {
        const int r = it * 8 + wid;
        float4 v0, v1;
        if (LEAF) {
            float4 xq = *(const float4*)&x[(size_t)(b0 + r) * DD + 4 * node];
            float4 ma0 = *(const float4*)&Pm[0 * 128 + 4 * lane];
            float4 ia0 = *(const float4*)&Pm[1 * 128 + 4 * lane];
            float4 mb0 = *(const float4*)&Pm[2 * 128 + 4 * lane];
            float4 ib0 = *(const float4*)&Pm[3 * 128 + 4 * lane];
            float4 cc0 = *(const float4*)&Pm[4 * 128 + 4 * lane];
            float4 ma1 = *(const float4*)&Pm[5 * 128 + 4 * lane];
            float4 ia1 = *(const float4*)&Pm[6 * 128 + 4 * lane];
            float4 mb1 = *(const float4*)&Pm[7 * 128 + 4 * lane];
            float4 ib1 = *(const float4*)&Pm[8 * 128 + 4 * lane];
            float4 cc1 = *(const float4*)&Pm[9 * 128 + 4 * lane];
            float t, u;
            t = (xq.x - ma0.x) * ia0.x; u = (xq.y - mb0.x) * ib0.x; v0.x = cc0.x - 0.5f * (t*t + u*u);
            t = (xq.x - ma0.y) * ia0.y; u = (xq.y - mb0.y) * ib0.y; v0.y = cc0.y - 0.5f * (t*t + u*u);
            t = (xq.x - ma0.z) * ia0.z; u = (xq.y - mb0.z) * ib0.z; v0.z = cc0.z - 0.5f * (t*t + u*u);
            t = (xq.x - ma0.w) * ia0.w; u = (xq.y - mb0.w) * ib0.w; v0.w = cc0.w - 0.5f * (t*t + u*u);
            t = (xq.z - ma1.x) * ia1.x; u = (xq.w - mb1.x) * ib1.x; v1.x = cc1.x - 0.5f * (t*t + u*u);
            t = (xq.z - ma1.y) * ia1.y; u = (xq.w - mb1.y) * ib1.y; v1.y = cc1.y - 0.5f * (t*t + u*u);
            t = (xq.z - ma1.z) * ia1.z; u = (xq.w - mb1.z) * ib1.z; v1.z = cc1.z - 0.5f * (t*t + u*u);
            t = (xq.z - ma1.w) * ia1.w; u = (xq.w - mb1.w) * ib1.w; v1.w = cc1.w - 0.5f * (t*t + u*u);
        } else {
            const float* yg = yin + ((size_t)(4 * node) * BATCH + b0 + r) * KK;
            float4 a = ((const float4*)yg)[lane];
            float4 b = ((const float4*)(yg + BK))[lane];
            float4 c = ((const float4*)(yg + 2 * BK))[lane];
            float4 d = ((const float4*)(yg + 3 * BK))[lane];
            v0.x = a.x + b.x; v0.y = a.y + b.y; v0.z = a.z + b.z; v0.w = a.w + b.w;
            v1.x = c.x + d.x; v1.y = c.y + d.y; v1.z = c.z + d.z; v1.w = c.w + d.w;
        }
        float m0 = warp_max(max4(v0));
        float m1 = warp_max(max4(v1));
        __half2 h0 = __floats2half2_rn(__expf(v0.x - m0), __expf(v0.y - m0));
        __half2 h1 = __floats2half2_rn(__expf(v0.z - m0), __expf(v0.w - m0));
        uint2 pk; pk.x = *(uint32_t*)&h0; pk.y = *(uint32_t*)&h1;
        *(uint2*)&As[r * LDA + 4 * lane] = pk;
        v1r[it] = v1; m0r[it] = m0; m1r[it] = m1;
    }

    AccFrag acc1[2], acc2[2];

    cp_wait<1>();
    __syncthreads();
    gemm32_acc(As, (const __half*)(smem + SM_W0), acc1, wid);
    __syncthreads();

    cp_wtile(sb + SM_W0, g_wh + (size_t)(wup + node) * (KK * KK), tid);

    #pragma unroll
    for (int it = 0; it < 4; it++)
        build_A_row(As, Msum, it * 8 + wid, lane, v1r[it], false, 0.0f);

    cp_wait<1>();
    __syncthreads();
    gemm32_acc(As, (const __half*)(smem + SM_W1), acc2, wid);

    #pragma unroll
    for (int j = 0; j < 2; j++)
        #pragma unroll
        for (int e = 0; e < acc2[j].num_elements; e++)
            acc2[j].x[e] *= acc1[j].x[e];
    store_acc(acc2, S0, wid);
    __syncthreads();

    #pragma unroll
    for (int it = 0; it < 4; it++) {
        const int r = it * 8 + wid;
        float4 p = *(const float4*)&S0[r * LDS + 4 * lane];
        float pmax = fmaxf(warp_max(max4(p)), 1e-35f);
        float inv = __fdividef(1.0f, pmax);
        float4 pn; pn.x = p.x * inv; pn.y = p.y * inv; pn.z = p.z * inv; pn.w = p.w * inv;
        __half2 h0 = __floats2half2_rn(pn.x, pn.y);
        __half2 h1 = __floats2half2_rn(pn.z, pn.w);
        uint2 pk; pk.x = *(uint32_t*)&h0; pk.y = *(uint32_t*)&h1;
        *(uint2*)&As[r * LDA + 4 * lane] = pk;
        if (lane == 0) Msum[r] = m0r[it] + m1r[it] + __logf(pmax);
    }

    cp_wait<0>();
    __syncthreads();
    gemm32_acc(As, (const __half*)(smem + SM_W0), acc2, wid);
    store_acc(acc2, S0, wid);
    __syncthreads();

    {
        const int r = tid >> 3, c0 = (tid & 7) * 16;
        const float mrow = Msum[r];
        float* orow = yout + ((size_t)node * BATCH + b0 + r) * KK + c0;
        #pragma unroll
        for (int c = 0; c < 4; c++) {
            float4 s = *(const float4*)&S0[r * LDS + c0 + 4 * c];
            float4 o;
            o.x = mrow + __logf(s.x); o.y = mrow + __logf(s.y);
            o.z = mrow + __logf(s.z); o.w = mrow + __logf(s.w);
            ((float4*)orow)[c] = o;
        }
    }
}

// ---------------- pair_fast: 3 W slots, all prefetched upfront (small grids) ----------------
__global__ void __launch_bounds__(256) pair_fast_kernel(
    int insel, int outsel, int wlo, int wup, float* __restrict__ dout)
{
    extern __shared__ char smem[];
    __half* As = (__half*)(smem + PF_A);
    float* S0  = (float*)(smem + PF_S0);
    float* Msum = (float*)(smem + PF_MSUM);
    const uint32_t sb = smem_u32(smem);

    const int tid = threadIdx.x, wid = tid >> 5, lane = tid & 31;
    const int node = blockIdx.y;
    const int b0 = blockIdx.x * 32;

    const float* yin = (insel == 0) ? g_buf0 : g_buf1;
    float* yout = (outsel == 0) ? g_buf0 : ((outsel == 1) ? g_buf1 : dout);

    cp_wtile(sb + PF_W0, g_wh + (size_t)(wlo + 2 * node) * (KK * KK), tid);
    cp_wtile(sb + PF_W1, g_wh + (size_t)(wlo + 2 * node + 1) * (KK * KK), tid);
    cp_wtile(sb + PF_W2, g_wh + (size_t)(wup + node) * (KK * KK), tid);

    float4 v1r[4];
    float m0r[4], m1r[4];
    #pragma unroll
    for (int it = 0; it < 4; it++) {
        const int r = it * 8 + wid;
        const float* yg = yin + ((size_t)(4 * node) * BATCH + b0 + r) * KK;
        float4 a = ((const float4*)yg)[lane];
        float4 b = ((const float4*)(yg + BK))[lane];
        float4 c = ((const float4*)(yg + 2 * BK))[lane];
        float4 d = ((const float4*)(yg + 3 * BK))[lane];
        float4 v0, v1;
        v0.x = a.x + b.x; v0.y = a.y + b.y; v0.z = a.z + b.z; v0.w = a.w + b.w;
        v1.x = c.x + d.x; v1.y = c.y + d.y; v1.z = c.z + d.z; v1.w = c.w + d.w;
        float m0 = warp_max(max4(v0));
        float m1 = warp_max(max4(v1));
        build_A_row(As, Msum, r, lane, v0, false, 0.0f);
        v1r[it] = v1; m0r[it] = m0; m1r[it] = m1;
    }

    AccFrag acc1[2], acc2[2];
    cp_wait<0>();
    __syncthreads();
    gemm32_acc(As, (const __half*)(smem + PF_W0), acc1, wid);
    __syncthreads();

    #pragma unroll
    for (int it = 0; it < 4; it++)
        build_A_row(As, Msum, it * 8 + wid, lane, v1r[it], false, 0.0f);
    __syncthreads();
    gemm32_acc(As, (const __half*)(smem + PF_W1), acc2, wid);

    #pragma unroll
    for (int j = 0; j < 2; j++)
        #pragma unroll
        for (int e = 0; e < acc2[j].num_elements; e++)
            acc2[j].x[e] *= acc1[j].x[e];
    store_acc(acc2, S0, wid);
    __syncthreads();

    #pragma unroll
    for (int it = 0; it < 4; it++) {
        const int r = it * 8 + wid;
        float4 p = *(const float4*)&S0[r * LDS + 4 * lane];
        float pmax = fmaxf(warp_max(max4(p)), 1e-35f);
        float inv = __fdividef(1.0f, pmax);
        __half2 h0 = __floats2half2_rn(p.x * inv, p.y * inv);
        __half2 h1 = __floats2half2_rn(p.z * inv, p.w * inv);
        uint2 pk; pk.x = *(uint32_t*)&h0; pk.y = *(uint32_t*)&h1;
        *(uint2*)&As[r * LDA + 4 * lane] = pk;
        if (lane == 0) Msum[r] = m0r[it] + m1r[it] + __logf(pmax);
    }
    __syncthreads();
    gemm32_acc(As, (const __half*)(smem + PF_W2), acc2, wid);
    store_acc(acc2, S0, wid);
    __syncthreads();

    {
        const int r = tid >> 3, c0 = (tid & 7) * 16;
        const float mrow = Msum[r];
        float* orow = yout + ((size_t)node * BATCH + b0 + r) * KK + c0;
        #pragma unroll
        for (int c = 0; c < 4; c++) {
            float4 s = *(const float4*)&S0[r * LDS + c0 + 4 * c];
            float4 o;
            o.x = mrow + __logf(s.x); o.y = mrow + __logf(s.y);
            o.z = mrow + __logf(s.z); o.w = mrow + __logf(s.w);
            ((float4*)orow)[c] = o;
        }
    }
}

// ---------------- pipelined tail: pairs (8+4) then (2+1), grid=8 ----------------
// 5 W slots: lo pairs double-buffered {0,1}/{2,3}, up slot 4.
__global__ void __launch_bounds__(256) tail_kernel(float* __restrict__ dout)
{
    extern __shared__ char smem[];
    __half* A0s = (__half*)(smem + TL_A0);
    __half* A1s = (__half*)(smem + TL_A1);
    float* S0  = (float*)(smem + TL_S0);
    float* Msum = (float*)(smem + TL_MSUM);
    const uint32_t sb = smem_u32(smem);

    const int tid = threadIdx.x, wid = tid >> 5, lane = tid & 31;
    const int b0 = blockIdx.x * 32;

    // pre-commit step0's 3 tiles: lo->slots{0,1}, up->slot4  (3 groups)
    cp_wtile(sb + 0 * WTILE, g_wh + (size_t)1008 * (KK * KK), tid);
    cp_wtile(sb + 1 * WTILE, g_wh + (size_t)1009 * (KK * KK), tid);
    cp_wtile(sb + 4 * WTILE, g_wh + (size_t)1016 * (KK * KK), tid);

    for (int s = 0; s < 5; s++) {
        const int node = (s < 4) ? s : 0;
        const float* yin = (s < 4) ? g_buf0 : g_buf1;
        float* yout = (s < 4) ? g_buf1 : dout;
        const int loPair = s & 1;

        // prefetch next step's lo tiles into the other pair (2 groups)
        if (s < 4) {
            const int ns = s + 1;
            const int nlo0 = (ns < 4) ? 1008 + 2 * ns : 1020;
            const int p = ns & 1;
            cp_wtile(sb + (2 * p + 0) * WTILE, g_wh + (size_t)(nlo0 + 0) * (KK * KK), tid);
            cp_wtile(sb + (2 * p + 1) * WTILE, g_wh + (size_t)(nlo0 + 1) * (KK * KK), tid);
        }

        // build both A tiles; Msum = m0+m1
        #pragma unroll
        for (int it = 0; it < 4; it++) {
            const int r = it * 8 + wid;
            const float* yg = yin + ((size_t)(4 * node) * BATCH + b0 + r) * KK;
            float4 a = ((const float4*)yg)[lane];
            float4 b = ((const float4*)(yg + BK))[lane];
            float4 c = ((const float4*)(yg + 2 * BK))[lane];
            float4 d = ((const float4*)(yg + 3 * BK))[lane];
            float4 v0, v1;
            v0.x = a.x + b.x; v0.y = a.y + b.y; v0.z = a.z + b.z; v0.w = a.w + b.w;
            v1.x = c.x + d.x; v1.y = c.y + d.y; v1.z = c.z + d.z; v1.w = c.w + d.w;
            float m0 = warp_max(max4(v0));
            float m1 = warp_max(max4(v1));
            __half2 h00 = __floats2half2_rn(__expf(v0.x - m0), __expf(v0.y - m0));
            __half2 h01 = __floats2half2_rn(__expf(v0.z - m0), __expf(v0.w - m0));
            __half2 h10 = __floats2half2_rn(__expf(v1.x - m1), __expf(v1.y - m1));
            __half2 h11 = __floats2half2_rn(__expf(v1.z - m1), __expf(v1.w - m1));
            uint2 p0; p0.x = *(uint32_t*)&h00; p0.y = *(uint32_t*)&h01;
            uint2 p1; p1.x = *(uint32_t*)&h10; p1.y = *(uint32_t*)&h11;
            *(uint2*)&A0s[r * LDA + 4 * lane] = p0;
            *(uint2*)&A1s[r * LDA + 4 * lane] = p1;
            if (lane == 0) Msum[r] = m0 + m1;
        }

        // wait: current step's 3 groups done (next lo's 2 groups may stay pending)
        if (s < 4) cp_wait<2>(); else cp_wait<0>();
        __syncthreads();

        AccFrag acc1[2], acc2[2];
        gemm32_acc(A0s, (const __half*)(smem + (2 * loPair + 0) * WTILE), acc1, wid);
        gemm32_acc(A1s, (const __half*)(smem + (2 * loPair + 1) * WTILE), acc2, wid);
        #pragma unroll
        for (int j = 0; j < 2; j++)
            #pragma unroll
            for (int e = 0; e < acc2[j].num_elements; e++)
                acc2[j].x[e] *= acc1[j].x[e];
        store_acc(acc2, S0, wid);
        __syncthreads();

        #pragma unroll
        for (int it = 0; it < 4; it++) {
            const int r = it * 8 + wid;
            float4 p = *(const float4*)&S0[r * LDS + 4 * lane];
            float pmax = fmaxf(warp_max(max4(p)), 1e-35f);
            float inv = __fdividef(1.0f, pmax);
            __half2 h0 = __floats2half2_rn(p.x * inv, p.y * inv);
            __half2 h1 = __floats2half2_rn(p.z * inv, p.w * inv);
            uint2 pk; pk.x = *(uint32_t*)&h0; pk.y = *(uint32_t*)&h1;
            *(uint2*)&A0s[r * LDA + 4 * lane] = pk;
            if (lane == 0) Msum[r] += __logf(pmax);
        }
        __syncthreads();

        gemm32_acc(A0s, (const __half*)(smem + 4 * WTILE), acc2, wid);
        store_acc(acc2, S0, wid);
        __syncthreads();         // GEMM3 done reading slot 4 -> safe to overwrite

        // prefetch next step's up tile into slot 4 (1 group)
        if (s < 4) {
            const int ns = s + 1;
            const int nup = (ns < 4) ? 1016 + ns : 1022;
            cp_wtile(sb + 4 * WTILE, g_wh + (size_t)nup * (KK * KK), tid);
        }

        // epilogue
        {
            const int r = tid >> 3, c0 = (tid & 7) * 16;
            const float mrow = Msum[r];
            float* orow = yout + ((size_t)node * BATCH + b0 + r) * KK + c0;
            #pragma unroll
            for (int c = 0; c < 4; c++) {
                float4 sv = *(const float4*)&S0[r * LDS + c0 + 4 * c];
                float4 o;
                o.x = mrow + __logf(sv.x); o.y = mrow + __logf(sv.y);
                o.z = mrow + __logf(sv.z); o.w = mrow + __logf(sv.w);
                ((float4*)orow)[c] = o;
            }
        }
        __syncthreads();   // global writes visible to next step's reads
    }
}

extern "C" void kernel_launch(void* const* d_in, const int* in_sizes, int n_in,
                              void* d_out, int out_size) {
    const float* x  = (const float*)d_in[0];
    const float* mu = (const float*)d_in[1];
    const float* ls = (const float*)d_in[2];
    const float* w  = (const float*)d_in[3];
    float* out = (float*)d_out;

    cudaFuncSetAttribute(pair_kernel<true>,  cudaFuncAttributeMaxDynamicSharedMemorySize, SMEM_BYTES);
    cudaFuncSetAttribute(pair_kernel<false>, cudaFuncAttributeMaxDynamicSharedMemorySize, SMEM_BYTES);
    cudaFuncSetAttribute(pair_fast_kernel, cudaFuncAttributeMaxDynamicSharedMemorySize, PF_BYTES);
    cudaFuncSetAttribute(tail_kernel, cudaFuncAttributeMaxDynamicSharedMemorySize, TL_BYTES);

    softmax_w_kernel<<<1023, 256>>>(w);

    pair_kernel<true ><<<dim3(8, 256), 256, SMEM_BYTES>>>(-1, 0, 0,   512, x, mu, ls, out); // -> buf0 (256)
    pair_kernel<false><<<dim3(8, 64),  256, SMEM_BYTES>>>( 0, 1, 768, 896, x, mu, ls, out); // -> buf1 (64)
    pair_fast_kernel  <<<dim3(8, 16),  256, PF_BYTES  >>>( 1, 0, 960, 992, out);            // -> buf0 (16)
    tail_kernel<<<8, 256, TL_BYTES>>>(out);                                                 // (8+4)+(2+1) -> out
}

// round 11
// speedup vs baseline: 1.0433x; 1.0433x over previous
#include <cuda_runtime.h>
#include <cuda_fp16.h>
#include <mma.h>
#include <stdint.h>

using namespace nvcuda;

#define KK 128
#define BATCH 256
#define DD 1024
#define BK (BATCH*KK)
#define LDA 136           // halves per A/W smem row (272 B)
#define LDS 132           // floats per S smem row
#define WTILE 34816

// static scratch (allocation-free rule)
__device__ float  g_buf0[512 * BATCH * KK];
__device__ float  g_buf1[256 * BATCH * KK];
__device__ __half g_wh[1023 * KK * KK];      // softmax(W) fp16

// ---- pair_lean smem layout (ONE W slot -> 3 blocks/SM) ----
#define PL_W    0          // [128][136] fp16 = 34816
#define PL_A    34816      // [32][136] fp16 = 8704
#define PL_S0   43520      // [32][132] f32 = 16896 (leaf params alias head)
#define PL_MSUM 60416      // [32] f32
#define PL_BYTES (PL_MSUM + 192)   // ~59.2 KB

// ---- pair_fast smem layout (3 W slots, grid<148 so smem free) ----
#define PF_W0   0
#define PF_W1   34816
#define PF_W2   69632
#define PF_A    104448
#define PF_S0   113152
#define PF_MSUM 130048
#define PF_BYTES (PF_MSUM + 192)

// ---------------- helpers ----------------
static __device__ __forceinline__ uint32_t smem_u32(const void* p) {
    uint32_t a;
    asm("{ .reg .u64 t; cvta.to.shared.u64 t, %1; cvt.u32.u64 %0, t; }" : "=r"(a) : "l"(p));
    return a;
}
static __device__ __forceinline__ void cp_async16(uint32_t dst, const void* src) {
    asm volatile("cp.async.cg.shared.global [%0], [%1], 16;" :: "r"(dst), "l"(src));
}
static __device__ __forceinline__ void cp_commit() {
    asm volatile("cp.async.commit_group;" ::: "memory");
}
template<int N> static __device__ __forceinline__ void cp_wait() {
    asm volatile("cp.async.wait_group %0;" :: "n"(N) : "memory");
}
static __device__ __forceinline__ float warp_max(float m) {
    #pragma unroll
    for (int o = 16; o; o >>= 1) m = fmaxf(m, __shfl_xor_sync(0xffffffffu, m, o));
    return m;
}
static __device__ __forceinline__ float max4(float4 v) {
    return fmaxf(fmaxf(v.x, v.y), fmaxf(v.z, v.w));
}

// ---------------- K0: softmax(W) -> fp16, all nodes ----------------
__global__ void __launch_bounds__(256) softmax_w_kernel(const float* __restrict__ w) {
    const int node = blockIdx.x;
    const int wid = threadIdx.x >> 5, lane = threadIdx.x & 31;
    const float* wn = w + (size_t)node * (KK * KK);
    __half* out = g_wh + (size_t)node * (KK * KK);
    for (int i = wid; i < KK; i += 8) {
        float4 v = ((const float4*)(wn + i * KK))[lane];
        float m = warp_max(max4(v));
        float e0 = __expf(v.x - m), e1 = __expf(v.y - m);
        float e2 = __expf(v.z - m), e3 = __expf(v.w - m);
        float s = e0 + e1 + e2 + e3;
        #pragma unroll
        for (int o = 16; o; o >>= 1) s += __shfl_xor_sync(0xffffffffu, s, o);
        float inv = 1.0f / s;
        __half2 h0 = __floats2half2_rn(e0 * inv, e1 * inv);
        __half2 h1 = __floats2half2_rn(e2 * inv, e3 * inv);
        uint2 pk; pk.x = *(uint32_t*)&h0; pk.y = *(uint32_t*)&h1;
        *(uint2*)&out[i * KK + 4 * lane] = pk;
    }
}

// in-register 32x128x128 GEMM: acc[m,i] = sum_j A[m,j]*W[i,j]; warp tile 16m x 32n
using AccFrag = wmma::fragment<wmma::accumulator, 16, 16, 16, float>;
static __device__ __forceinline__ void gemm32_acc(const __half* As, const __half* Wh,
                                                  AccFrag acc[2], int wid) {
    const int warp_m = wid & 1, warp_n = wid >> 1;
    const int m_base = warp_m * 16, n_base = warp_n * 32;
    wmma::fill_fragment(acc[0], 0.0f);
    wmma::fill_fragment(acc[1], 0.0f);
    #pragma unroll
    for (int k = 0; k < 8; k++) {
        wmma::fragment<wmma::matrix_a, 16, 16, 16, __half, wmma::row_major> af;
        wmma::load_matrix_sync(af, &As[m_base * LDA + 16 * k], LDA);
        #pragma unroll
        for (int j = 0; j < 2; j++) {
            wmma::fragment<wmma::matrix_b, 16, 16, 16, __half, wmma::col_major> bf;
            wmma::load_matrix_sync(bf, &Wh[(n_base + 16 * j) * LDA + 16 * k], LDA);
            wmma::mma_sync(acc[j], af, bf, acc[j]);
        }
    }
}
static __device__ __forceinline__ void store_acc(AccFrag acc[2], float* Out, int wid) {
    const int warp_m = wid & 1, warp_n = wid >> 1;
    #pragma unroll
    for (int j = 0; j < 2; j++)
        wmma::store_matrix_sync(&Out[(warp_m * 16) * LDS + warp_n * 32 + 16 * j],
                                acc[j], LDS, wmma::mem_row_major);
}
static __device__ __forceinline__ void cp_wtile(uint32_t dst, const __half* wsrc, int tid) {
    const char* ws = (const char*)wsrc;
    #pragma unroll
    for (int c = tid; c < 2048; c += 256)
        cp_async16(dst + (c >> 4) * 272 + (c & 15) * 16, ws + (c >> 4) * 256 + (c & 15) * 16);
    cp_commit();
}
static __device__ __forceinline__ void build_A_row(
    __half* dst, int r, int lane, float4 v, float m)
{
    __half2 h0 = __floats2half2_rn(__expf(v.x - m), __expf(v.y - m));
    __half2 h1 = __floats2half2_rn(__expf(v.z - m), __expf(v.w - m));
    uint2 pk; pk.x = *(uint32_t*)&h0; pk.y = *(uint32_t*)&h1;
    *(uint2*)&dst[r * LDA + 4 * lane] = pk;
}

// ---------------- pair_lean: ONE W slot, 3 blocks/SM (big grids) ----------------
template<bool LEAF>
__global__ void __launch_bounds__(256, 3) pair_lean_kernel(
    int insel, int outsel, int wlo, int wup,
    const float* __restrict__ x, const float* __restrict__ mu,
    const float* __restrict__ ls, float* __restrict__ dout)
{
    extern __shared__ char smem[];
    __half* Wh = (__half*)(smem + PL_W);
    __half* As = (__half*)(smem + PL_A);
    float* S0  = (float*)(smem + PL_S0);
    float* Pm  = (float*)(smem + PL_S0);     // leaf params alias S0 (dead until product store)
    float* Msum = (float*)(smem + PL_MSUM);
    const uint32_t sb = smem_u32(smem);

    const int tid = threadIdx.x, wid = tid >> 5, lane = tid & 31;
    const int node = blockIdx.y;
    const int b0 = blockIdx.x * 32;

    const float* yin = (insel == 0) ? g_buf0 : g_buf1;
    float* yout = (outsel == 0) ? g_buf0 : ((outsel == 1) ? g_buf1 : dout);

    cp_wtile(sb + PL_W, g_wh + (size_t)(wlo + 2 * node) * (KK * KK), tid);   // W_c0

    if (LEAF) {
        if (tid < 128) {
            int v0 = 4 * node, v1 = 4 * node + 1, v2 = 4 * node + 2, v3 = 4 * node + 3;
            float l0 = ls[v0 * KK + tid], l1 = ls[v1 * KK + tid];
            float l2 = ls[v2 * KK + tid], l3 = ls[v3 * KK + tid];
            Pm[0 * 128 + tid] = mu[v0 * KK + tid];
            Pm[1 * 128 + tid] = __expf(-l0);
            Pm[2 * 128 + tid] = mu[v1 * KK + tid];
            Pm[3 * 128 + tid] = __expf(-l1);
            Pm[4 * 128 + tid] = -l0 - l1 - 1.8378770664093453f;
            Pm[5 * 128 + tid] = mu[v2 * KK + tid];
            Pm[6 * 128 + tid] = __expf(-l2);
            Pm[7 * 128 + tid] = mu[v3 * KK + tid];
            Pm[8 * 128 + tid] = __expf(-l3);
            Pm[9 * 128 + tid] = -l2 - l3 - 1.8378770664093453f;
        }
        __syncthreads();
    }

    // ---- build A0 into smem; hold v1/m0/m1 in registers ----
    float4 v1r[4];
    float m0r[4], m1r[4];
    #pragma unroll
    for (int it = 0; it < 4; it++) {
        const int r = it * 8 + wid;
        float4 v0, v1;
        if (LEAF) {
            float4 xq = *(const float4*)&x[(size_t)(b0 + r) * DD + 4 * node];
            float4 ma0 = *(const float4*)&Pm[0 * 128 + 4 * lane];
            float4 ia0 = *(const float4*)&Pm[1 * 128 + 4 * lane];
            float4 mb0 = *(const float4*)&Pm[2 * 128 + 4 * lane];
            float4 ib0 = *(const float4*)&Pm[3 * 128 + 4 * lane];
            float4 cc0 = *(const float4*)&Pm[4 * 128 + 4 * lane];
            float4 ma1 = *(const float4*)&Pm[5 * 128 + 4 * lane];
            float4 ia1 = *(const float4*)&Pm[6 * 128 + 4 * lane];
            float4 mb1 = *(const float4*)&Pm[7 * 128 + 4 * lane];
            float4 ib1 = *(const float4*)&Pm[8 * 128 + 4 * lane];
            float4 cc1 = *(const float4*)&Pm[9 * 128 + 4 * lane];
            float t, u;
            t = (xq.x - ma0.x) * ia0.x; u = (xq.y - mb0.x) * ib0.x; v0.x = cc0.x - 0.5f * (t*t + u*u);
            t = (xq.x - ma0.y) * ia0.y; u = (xq.y - mb0.y) * ib0.y; v0.y = cc0.y - 0.5f * (t*t + u*u);
            t = (xq.x - ma0.z) * ia0.z; u = (xq.y - mb0.z) * ib0.z; v0.z = cc0.z - 0.5f * (t*t + u*u);
            t = (xq.x - ma0.w) * ia0.w; u = (xq.y - mb0.w) * ib0.w; v0.w = cc0.w - 0.5f * (t*t + u*u);
            t = (xq.z - ma1.x) * ia1.x; u = (xq.w - mb1.x) * ib1.x; v1.x = cc1.x - 0.5f * (t*t + u*u);
            t = (xq.z - ma1.y) * ia1.y; u = (xq.w - mb1.y) * ib1.y; v1.y = cc1.y - 0.5f * (t*t + u*u);
            t = (xq.z - ma1.z) * ia1.z; u = (xq.w - mb1.z) * ib1.z; v1.z = cc1.z - 0.5f * (t*t + u*u);
            t = (xq.z - ma1.w) * ia1.w; u = (xq.w - mb1.w) * ib1.w; v1.w = cc1.w - 0.5f * (t*t + u*u);
        } else {
            const float* yg = yin + ((size_t)(4 * node) * BATCH + b0 + r) * KK;
            float4 a = ((const float4*)yg)[lane];
            float4 b = ((const float4*)(yg + BK))[lane];
            float4 c = ((const float4*)(yg + 2 * BK))[lane];
            float4 d = ((const float4*)(yg + 3 * BK))[lane];
            v0.x = a.x + b.x; v0.y = a.y + b.y; v0.z = a.z + b.z; v0.w = a.w + b.w;
            v1.x = c.x + d.x; v1.y = c.y + d.y; v1.z = c.z + d.z; v1.w = c.w + d.w;
        }
        float m0 = warp_max(max4(v0));
        float m1 = warp_max(max4(v1));
        build_A_row(As, it * 8 + wid, lane, v0, m0);
        v1r[it] = v1; m0r[it] = m0; m1r[it] = m1;
    }

    AccFrag acc1[2], acc2[2];

    cp_wait<0>();            // W_c0 ready
    __syncthreads();
    gemm32_acc(As, Wh, acc1, wid);
    __syncthreads();         // done reading As + Wh

    cp_wtile(sb + PL_W, g_wh + (size_t)(wlo + 2 * node + 1) * (KK * KK), tid);   // W_c1

    // A1 from registers
    #pragma unroll
    for (int it = 0; it < 4; it++)
        build_A_row(As, it * 8 + wid, lane, v1r[it], m1r[it]);

    cp_wait<0>();            // W_c1 ready
    __syncthreads();
    gemm32_acc(As, Wh, acc2, wid);

    // fragment-space product
    #pragma unroll
    for (int j = 0; j < 2; j++)
        #pragma unroll
        for (int e = 0; e < acc2[j].num_elements; e++)
            acc2[j].x[e] *= acc1[j].x[e];
    __syncthreads();         // done reading Wh/As

    cp_wtile(sb + PL_W, g_wh + (size_t)(wup + node) * (KK * KK), tid);           // W_up
    store_acc(acc2, S0, wid);
    __syncthreads();

    // ---- renorm -> As, Msum ----
    #pragma unroll
    for (int it = 0; it < 4; it++) {
        const int r = it * 8 + wid;
        float4 p = *(const float4*)&S0[r * LDS + 4 * lane];
        float pmax = fmaxf(warp_max(max4(p)), 1e-35f);
        float inv = __fdividef(1.0f, pmax);
        __half2 h0 = __floats2half2_rn(p.x * inv, p.y * inv);
        __half2 h1 = __floats2half2_rn(p.z * inv, p.w * inv);
        uint2 pk; pk.x = *(uint32_t*)&h0; pk.y = *(uint32_t*)&h1;
        *(uint2*)&As[r * LDA + 4 * lane] = pk;
        if (lane == 0) Msum[r] = m0r[it] + m1r[it] + __logf(pmax);
    }

    cp_wait<0>();            // W_up ready
    __syncthreads();
    gemm32_acc(As, Wh, acc2, wid);
    store_acc(acc2, S0, wid);
    __syncthreads();

    // ---- epilogue ----
    {
        const int r = tid >> 3, c0 = (tid & 7) * 16;
        const float mrow = Msum[r];
        float* orow = yout + ((size_t)node * BATCH + b0 + r) * KK + c0;
        #pragma unroll
        for (int c = 0; c < 4; c++) {
            float4 s = *(const float4*)&S0[r * LDS + c0 + 4 * c];
            float4 o;
            o.x = mrow + __logf(s.x); o.y = mrow + __logf(s.y);
            o.z = mrow + __logf(s.z); o.w = mrow + __logf(s.w);
            ((float4*)orow)[c] = o;
        }
    }
}

// ---------------- pair_fast: 3 W slots upfront (grid < 148) ----------------
__global__ void __launch_bounds__(256) pair_fast_kernel(
    int insel, int outsel, int wlo, int wup, float* __restrict__ dout)
{
    extern __shared__ char smem[];
    __half* As = (__half*)(smem + PF_A);
    float* S0  = (float*)(smem + PF_S0);
    float* Msum = (float*)(smem + PF_MSUM);
    const uint32_t sb = smem_u32(smem);

    const int tid = threadIdx.x, wid = tid >> 5, lane = tid & 31;
    const int node = blockIdx.y;
    const int b0 = blockIdx.x * 32;

    const float* yin = (insel == 0) ? g_buf0 : g_buf1;
    float* yout = (outsel == 0) ? g_buf0 : ((outsel == 1) ? g_buf1 : dout);

    cp_wtile(sb + PF_W0, g_wh + (size_t)(wlo + 2 * node) * (KK * KK), tid);
    cp_wtile(sb + PF_W1, g_wh + (size_t)(wlo + 2 * node + 1) * (KK * KK), tid);
    cp_wtile(sb + PF_W2, g_wh + (size_t)(wup + node) * (KK * KK), tid);

    float4 v1r[4];
    float m0r[4], m1r[4];
    #pragma unroll
    for (int it = 0; it < 4; it++) {
        const int r = it * 8 + wid;
        const float* yg = yin + ((size_t)(4 * node) * BATCH + b0 + r) * KK;
        float4 a = ((const float4*)yg)[lane];
        float4 b = ((const float4*)(yg + BK))[lane];
        float4 c = ((const float4*)(yg + 2 * BK))[lane];
        float4 d = ((const float4*)(yg + 3 * BK))[lane];
        float4 v0, v1;
        v0.x = a.x + b.x; v0.y = a.y + b.y; v0.z = a.z + b.z; v0.w = a.w + b.w;
        v1.x = c.x + d.x; v1.y = c.y + d.y; v1.z = c.z + d.z; v1.w = c.w + d.w;
        float m0 = warp_max(max4(v0));
        float m1 = warp_max(max4(v1));
        build_A_row(As, r, lane, v0, m0);
        v1r[it] = v1; m0r[it] = m0; m1r[it] = m1;
    }

    AccFrag acc1[2], acc2[2];
    cp_wait<0>();
    __syncthreads();
    gemm32_acc(As, (const __half*)(smem + PF_W0), acc1, wid);
    __syncthreads();

    #pragma unroll
    for (int it = 0; it < 4; it++)
        build_A_row(As, it * 8 + wid, lane, v1r[it], m1r[it]);
    __syncthreads();
    gemm32_acc(As, (const __half*)(smem + PF_W1), acc2, wid);

    #pragma unroll
    for (int j = 0; j < 2; j++)
        #pragma unroll
        for (int e = 0; e < acc2[j].num_elements; e++)
            acc2[j].x[e] *= acc1[j].x[e];
    store_acc(acc2, S0, wid);
    __syncthreads();

    #pragma unroll
    for (int it = 0; it < 4; it++) {
        const int r = it * 8 + wid;
        float4 p = *(const float4*)&S0[r * LDS + 4 * lane];
        float pmax = fmaxf(warp_max(max4(p)), 1e-35f);
        float inv = __fdividef(1.0f, pmax);
        __half2 h0 = __floats2half2_rn(p.x * inv, p.y * inv);
        __half2 h1 = __floats2half2_rn(p.z * inv, p.w * inv);
        uint2 pk; pk.x = *(uint32_t*)&h0; pk.y = *(uint32_t*)&h1;
        *(uint2*)&As[r * LDA + 4 * lane] = pk;
        if (lane == 0) Msum[r] = m0r[it] + m1r[it] + __logf(pmax);
    }
    __syncthreads();
    gemm32_acc(As, (const __half*)(smem + PF_W2), acc2, wid);
    store_acc(acc2, S0, wid);
    __syncthreads();

    {
        const int r = tid >> 3, c0 = (tid & 7) * 16;
        const float mrow = Msum[r];
        float* orow = yout + ((size_t)node * BATCH + b0 + r) * KK + c0;
        #pragma unroll
        for (int c = 0; c < 4; c++) {
            float4 s = *(const float4*)&S0[r * LDS + c0 + 4 * c];
            float4 o;
            o.x = mrow + __logf(s.x); o.y = mrow + __logf(s.y);
            o.z = mrow + __logf(s.z); o.w = mrow + __logf(s.w);
            ((float4*)orow)[c] = o;
        }
    }
}

extern "C" void kernel_launch(void* const* d_in, const int* in_sizes, int n_in,
                              void* d_out, int out_size) {
    const float* x  = (const float*)d_in[0];
    const float* mu = (const float*)d_in[1];
    const float* ls = (const float*)d_in[2];
    const float* w  = (const float*)d_in[3];
    float* out = (float*)d_out;

    cudaFuncSetAttribute(pair_lean_kernel<true>,  cudaFuncAttributeMaxDynamicSharedMemorySize, PL_BYTES);
    cudaFuncSetAttribute(pair_lean_kernel<false>, cudaFuncAttributeMaxDynamicSharedMemorySize, PL_BYTES);
    cudaFuncSetAttribute(pair_fast_kernel, cudaFuncAttributeMaxDynamicSharedMemorySize, PF_BYTES);

    softmax_w_kernel<<<1023, 256>>>(w);

    // pairs: (leaf512+256) (128+64) (32+16) (8+4) (2+1)
    pair_lean_kernel<true ><<<dim3(8, 256), 256, PL_BYTES>>>(-1, 0, 0,   512, x, mu, ls, out); // -> buf0 (256)
    pair_lean_kernel<false><<<dim3(8, 64),  256, PL_BYTES>>>( 0, 1, 768, 896, x, mu, ls, out); // -> buf1 (64)
    pair_fast_kernel<<<dim3(8, 16), 256, PF_BYTES>>>( 1, 0, 960,  992,  out);                  // -> buf0 (16)
    pair_fast_kernel<<<dim3(8, 4),  256, PF_BYTES>>>( 0, 1, 1008, 1016, out);                  // -> buf1 (4)
    pair_fast_kernel<<<dim3(8, 1),  256, PF_BYTES>>>( 1, 2, 1020, 1022, out);                  // -> out (root)
}

// round 12
// speedup vs baseline: 1.2067x; 1.1566x over previous
#include <cuda_runtime.h>
#include <cuda_fp16.h>
#include <mma.h>
#include <stdint.h>

using namespace nvcuda;

#define KK 128
#define BATCH 256
#define DD 1024
#define BK (BATCH*KK)
#define LDA 136           // halves per A/W smem row (272 B)
#define LDS 132           // floats per S smem row

// static scratch (allocation-free rule)
__device__ float  g_buf0[512 * BATCH * KK];
__device__ float  g_buf1[256 * BATCH * KK];
__device__ __half g_wh[1023 * KK * KK];      // softmax(W) fp16

// ---- R7 pair smem layout (32 rows) ----
#define SM_W0   0
#define SM_W1   34816
#define SM_A    69632
#define SM_S0   78336
#define SM_MSUM 95232
#define SMEM_BYTES (SM_MSUM + 192)

// ---- pair64 smem layout (64 rows) ----
#define P64_W0   0          // [128][136] fp16
#define P64_W1   34816      // [128][136] fp16; renormalized A aliases this after GEMM2
#define P64_AR   34816      // alias of W1
#define P64_A0   69632      // [64][136] fp16 = 17408
#define P64_A1   87040      // [64][136] fp16 = 17408
#define P64_S0   69632      // [64][132] f32 = 33792, alias A0+A1
#define P64_MSUM 104448     // [64] f32
#define P64_PM   104704     // leaf params 10x128 f32 = 5120
#define P64_BYTES (P64_PM + 5120 + 64)   // ~107.3 KB -> 2 blocks/SM

// ---------------- helpers ----------------
static __device__ __forceinline__ uint32_t smem_u32(const void* p) {
    uint32_t a;
    asm("{ .reg .u64 t; cvta.to.shared.u64 t, %1; cvt.u32.u64 %0, t; }" : "=r"(a) : "l"(p));
    return a;
}
static __device__ __forceinline__ void cp_async16(uint32_t dst, const void* src) {
    asm volatile("cp.async.cg.shared.global [%0], [%1], 16;" :: "r"(dst), "l"(src));
}
static __device__ __forceinline__ void cp_commit() {
    asm volatile("cp.async.commit_group;" ::: "memory");
}
template<int N> static __device__ __forceinline__ void cp_wait() {
    asm volatile("cp.async.wait_group %0;" :: "n"(N) : "memory");
}
static __device__ __forceinline__ float warp_max(float m) {
    #pragma unroll
    for (int o = 16; o; o >>= 1) m = fmaxf(m, __shfl_xor_sync(0xffffffffu, m, o));
    return m;
}
static __device__ __forceinline__ float max4(float4 v) {
    return fmaxf(fmaxf(v.x, v.y), fmaxf(v.z, v.w));
}

// ---------------- K0: softmax(W) -> fp16 ----------------
__global__ void __launch_bounds__(256) softmax_w_kernel(const float* __restrict__ w) {
    const int node = blockIdx.x;
    const int wid = threadIdx.x >> 5, lane = threadIdx.x & 31;
    const float* wn = w + (size_t)node * (KK * KK);
    __half* out = g_wh + (size_t)node * (KK * KK);
    for (int i = wid; i < KK; i += 8) {
        float4 v = ((const float4*)(wn + i * KK))[lane];
        float m = warp_max(max4(v));
        float e0 = __expf(v.x - m), e1 = __expf(v.y - m);
        float e2 = __expf(v.z - m), e3 = __expf(v.w - m);
        float s = e0 + e1 + e2 + e3;
        #pragma unroll
        for (int o = 16; o; o >>= 1) s += __shfl_xor_sync(0xffffffffu, s, o);
        float inv = 1.0f / s;
        __half2 h0 = __floats2half2_rn(e0 * inv, e1 * inv);
        __half2 h1 = __floats2half2_rn(e2 * inv, e3 * inv);
        uint2 pk; pk.x = *(uint32_t*)&h0; pk.y = *(uint32_t*)&h1;
        *(uint2*)&out[i * KK + 4 * lane] = pk;
    }
}

using AccFrag = wmma::fragment<wmma::accumulator, 16, 16, 16, float>;

// 32x128x128: warp tile 16m x 32n
static __device__ __forceinline__ void gemm32_acc(const __half* As, const __half* Wh,
                                                  AccFrag acc[2], int wid) {
    const int m_base = (wid & 1) * 16, n_base = (wid >> 1) * 32;
    wmma::fill_fragment(acc[0], 0.0f);
    wmma::fill_fragment(acc[1], 0.0f);
    #pragma unroll
    for (int k = 0; k < 8; k++) {
        wmma::fragment<wmma::matrix_a, 16, 16, 16, __half, wmma::row_major> af;
        wmma::load_matrix_sync(af, &As[m_base * LDA + 16 * k], LDA);
        #pragma unroll
        for (int j = 0; j < 2; j++) {
            wmma::fragment<wmma::matrix_b, 16, 16, 16, __half, wmma::col_major> bf;
            wmma::load_matrix_sync(bf, &Wh[(n_base + 16 * j) * LDA + 16 * k], LDA);
            wmma::mma_sync(acc[j], af, bf, acc[j]);
        }
    }
}
static __device__ __forceinline__ void store_acc32(AccFrag acc[2], float* Out, int wid) {
    const int m_base = (wid & 1) * 16, n_base = (wid >> 1) * 32;
    #pragma unroll
    for (int j = 0; j < 2; j++)
        wmma::store_matrix_sync(&Out[m_base * LDS + n_base + 16 * j], acc[j], LDS,
                                wmma::mem_row_major);
}

// 64x128x128: warp grid 2m x 4n, warp tile 32m x 32n (2x2 frags, flattened [4])
static __device__ __forceinline__ void gemm64_acc(const __half* As, const __half* Wh,
                                                  AccFrag acc[4], int wid) {
    const int m_base = (wid & 1) * 32, n_base = (wid >> 1) * 32;
    #pragma unroll
    for (int i = 0; i < 4; i++) wmma::fill_fragment(acc[i], 0.0f);
    #pragma unroll
    for (int k = 0; k < 8; k++) {
        wmma::fragment<wmma::matrix_a, 16, 16, 16, __half, wmma::row_major> af[2];
        wmma::fragment<wmma::matrix_b, 16, 16, 16, __half, wmma::col_major> bf[2];
        #pragma unroll
        for (int i = 0; i < 2; i++)
            wmma::load_matrix_sync(af[i], &As[(m_base + 16 * i) * LDA + 16 * k], LDA);
        #pragma unroll
        for (int j = 0; j < 2; j++)
            wmma::load_matrix_sync(bf[j], &Wh[(n_base + 16 * j) * LDA + 16 * k], LDA);
        #pragma unroll
        for (int i = 0; i < 2; i++)
            #pragma unroll
            for (int j = 0; j < 2; j++)
                wmma::mma_sync(acc[2 * i + j], af[i], bf[j], acc[2 * i + j]);
    }
}
static __device__ __forceinline__ void store_acc64(AccFrag acc[4], float* Out, int wid) {
    const int m_base = (wid & 1) * 32, n_base = (wid >> 1) * 32;
    #pragma unroll
    for (int i = 0; i < 2; i++)
        #pragma unroll
        for (int j = 0; j < 2; j++)
            wmma::store_matrix_sync(&Out[(m_base + 16 * i) * LDS + n_base + 16 * j],
                                    acc[2 * i + j], LDS, wmma::mem_row_major);
}
static __device__ __forceinline__ void cp_wtile(uint32_t dst, const __half* wsrc, int tid) {
    const char* ws = (const char*)wsrc;
    #pragma unroll
    for (int c = tid; c < 2048; c += 256)
        cp_async16(dst + (c >> 4) * 272 + (c & 15) * 16, ws + (c >> 4) * 256 + (c & 15) * 16);
    cp_commit();
}
static __device__ __forceinline__ void build_A_row(
    __half* dst, int r, int lane, float4 v, float m)
{
    __half2 h0 = __floats2half2_rn(__expf(v.x - m), __expf(v.y - m));
    __half2 h1 = __floats2half2_rn(__expf(v.z - m), __expf(v.w - m));
    uint2 pk; pk.x = *(uint32_t*)&h0; pk.y = *(uint32_t*)&h1;
    *(uint2*)&dst[r * LDA + 4 * lane] = pk;
}

// ---------------- pair64: 64-row blocks for big levels ----------------
template<bool LEAF>
__global__ void __launch_bounds__(256, 2) pair64_kernel(
    int insel, int outsel, int wlo, int wup,
    const float* __restrict__ x, const float* __restrict__ mu,
    const float* __restrict__ ls, float* __restrict__ dout)
{
    extern __shared__ char smem[];
    __half* A0s = (__half*)(smem + P64_A0);
    __half* A1s = (__half*)(smem + P64_A1);
    __half* ARs = (__half*)(smem + P64_AR);
    float* S0  = (float*)(smem + P64_S0);
    float* Msum = (float*)(smem + P64_MSUM);
    float* Pm  = (float*)(smem + P64_PM);
    const uint32_t sb = smem_u32(smem);

    const int tid = threadIdx.x, wid = tid >> 5, lane = tid & 31;
    const int node = blockIdx.y;
    const int b0 = blockIdx.x * 64;

    const float* yin = (insel == 0) ? g_buf0 : g_buf1;
    float* yout = (outsel == 0) ? g_buf0 : ((outsel == 1) ? g_buf1 : dout);

    cp_wtile(sb + P64_W0, g_wh + (size_t)(wlo + 2 * node) * (KK * KK), tid);
    cp_wtile(sb + P64_W1, g_wh + (size_t)(wlo + 2 * node + 1) * (KK * KK), tid);

    if (LEAF) {
        if (tid < 128) {
            int v0 = 4 * node, v1 = 4 * node + 1, v2 = 4 * node + 2, v3 = 4 * node + 3;
            float l0 = ls[v0 * KK + tid], l1 = ls[v1 * KK + tid];
            float l2 = ls[v2 * KK + tid], l3 = ls[v3 * KK + tid];
            Pm[0 * 128 + tid] = mu[v0 * KK + tid];
            Pm[1 * 128 + tid] = __expf(-l0);
            Pm[2 * 128 + tid] = mu[v1 * KK + tid];
            Pm[3 * 128 + tid] = __expf(-l1);
            Pm[4 * 128 + tid] = -l0 - l1 - 1.8378770664093453f;
            Pm[5 * 128 + tid] = mu[v2 * KK + tid];
            Pm[6 * 128 + tid] = __expf(-l2);
            Pm[7 * 128 + tid] = mu[v3 * KK + tid];
            Pm[8 * 128 + tid] = __expf(-l3);
            Pm[9 * 128 + tid] = -l2 - l3 - 1.8378770664093453f;
        }
        __syncthreads();
    }

    // ---- build BOTH A tiles (8 rows per warp); Msum[r] = m0+m1 ----
    #pragma unroll
    for (int it = 0; it < 8; it++) {
        const int r = it * 8 + wid;
        float4 v0, v1;
        if (LEAF) {
            float4 xq = *(const float4*)&x[(size_t)(b0 + r) * DD + 4 * node];
            float4 ma0 = *(const float4*)&Pm[0 * 128 + 4 * lane];
            float4 ia0 = *(const float4*)&Pm[1 * 128 + 4 * lane];
            float4 mb0 = *(const float4*)&Pm[2 * 128 + 4 * lane];
            float4 ib0 = *(const float4*)&Pm[3 * 128 + 4 * lane];
            float4 cc0 = *(const float4*)&Pm[4 * 128 + 4 * lane];
            float4 ma1 = *(const float4*)&Pm[5 * 128 + 4 * lane];
            float4 ia1 = *(const float4*)&Pm[6 * 128 + 4 * lane];
            float4 mb1 = *(const float4*)&Pm[7 * 128 + 4 * lane];
            float4 ib1 = *(const float4*)&Pm[8 * 128 + 4 * lane];
            float4 cc1 = *(const float4*)&Pm[9 * 128 + 4 * lane];
            float t, u;
            t = (xq.x - ma0.x) * ia0.x; u = (xq.y - mb0.x) * ib0.x; v0.x = cc0.x - 0.5f * (t*t + u*u);
            t = (xq.x - ma0.y) * ia0.y; u = (xq.y - mb0.y) * ib0.y; v0.y = cc0.y - 0.5f * (t*t + u*u);
            t = (xq.x - ma0.z) * ia0.z; u = (xq.y - mb0.z) * ib0.z; v0.z = cc0.z - 0.5f * (t*t + u*u);
            t = (xq.x - ma0.w) * ia0.w; u = (xq.y - mb0.w) * ib0.w; v0.w = cc0.w - 0.5f * (t*t + u*u);
            t = (xq.z - ma1.x) * ia1.x; u = (xq.w - mb1.x) * ib1.x; v1.x = cc1.x - 0.5f * (t*t + u*u);
            t = (xq.z - ma1.y) * ia1.y; u = (xq.w - mb1.y) * ib1.y; v1.y = cc1.y - 0.5f * (t*t + u*u);
            t = (xq.z - ma1.z) * ia1.z; u = (xq.w - mb1.z) * ib1.z; v1.z = cc1.z - 0.5f * (t*t + u*u);
            t = (xq.z - ma1.w) * ia1.w; u = (xq.w - mb1.w) * ib1.w; v1.w = cc1.w - 0.5f * (t*t + u*u);
        } else {
            const float* yg = yin + ((size_t)(4 * node) * BATCH + b0 + r) * KK;
            float4 a = ((const float4*)yg)[lane];
            float4 b = ((const float4*)(yg + BK))[lane];
            float4 c = ((const float4*)(yg + 2 * BK))[lane];
            float4 d = ((const float4*)(yg + 3 * BK))[lane];
            v0.x = a.x + b.x; v0.y = a.y + b.y; v0.z = a.z + b.z; v0.w = a.w + b.w;
            v1.x = c.x + d.x; v1.y = c.y + d.y; v1.z = c.z + d.z; v1.w = c.w + d.w;
        }
        float m0 = warp_max(max4(v0));
        float m1 = warp_max(max4(v1));
        build_A_row(A0s, r, lane, v0, m0);
        build_A_row(A1s, r, lane, v1, m1);
        if (lane == 0) Msum[r] = m0 + m1;
    }

    AccFrag acc1[4], acc2[4];

    cp_wait<0>();            // W_c0 + W_c1 ready
    __syncthreads();

    gemm64_acc(A0s, (const __half*)(smem + P64_W0), acc1, wid);
    gemm64_acc(A1s, (const __half*)(smem + P64_W1), acc2, wid);

    // fragment-space product
    #pragma unroll
    for (int i = 0; i < 4; i++)
        #pragma unroll
        for (int e = 0; e < acc2[i].num_elements; e++)
            acc2[i].x[e] *= acc1[i].x[e];

    __syncthreads();         // all warps done reading W0/W1/A0/A1
    cp_wtile(sb + P64_W0, g_wh + (size_t)(wup + node) * (KK * KK), tid);   // W_up -> W0
    store_acc64(acc2, S0, wid);      // S0 aliases A0+A1 (dead)
    __syncthreads();

    // ---- renorm: E' = P/rowmax -> ARs (aliases dead W1), Msum += log(rowmax) ----
    #pragma unroll
    for (int it = 0; it < 8; it++) {
        const int r = it * 8 + wid;
        float4 p = *(const float4*)&S0[r * LDS + 4 * lane];
        float pmax = fmaxf(warp_max(max4(p)), 1e-35f);
        float inv = __fdividef(1.0f, pmax);
        __half2 h0 = __floats2half2_rn(p.x * inv, p.y * inv);
        __half2 h1 = __floats2half2_rn(p.z * inv, p.w * inv);
        uint2 pk; pk.x = *(uint32_t*)&h0; pk.y = *(uint32_t*)&h1;
        *(uint2*)&ARs[r * LDA + 4 * lane] = pk;
        if (lane == 0) Msum[r] += __logf(pmax);
    }

    cp_wait<0>();            // W_up ready
    __syncthreads();
    gemm64_acc(ARs, (const __half*)(smem + P64_W0), acc1, wid);
    store_acc64(acc1, S0, wid);
    __syncthreads();

    // ---- epilogue: 4 threads/row, 32 cols each ----
    {
        const int r = tid >> 2, c0 = (tid & 3) * 32;
        const float mrow = Msum[r];
        float* orow = yout + ((size_t)node * BATCH + b0 + r) * KK + c0;
        #pragma unroll
        for (int c = 0; c < 8; c++) {
            float4 s = *(const float4*)&S0[r * LDS + c0 + 4 * c];
            float4 o;
            o.x = mrow + __logf(s.x); o.y = mrow + __logf(s.y);
            o.z = mrow + __logf(s.z); o.w = mrow + __logf(s.w);
            ((float4*)orow)[c] = o;
        }
    }
}

// ---------------- R7 pair kernel (32 rows) — small levels, verbatim flow ----------------
__global__ void __launch_bounds__(256, 2) pair_kernel(
    int insel, int outsel, int wlo, int wup, float* __restrict__ dout)
{
    extern __shared__ char smem[];
    __half* As = (__half*)(smem + SM_A);
    float* S0  = (float*)(smem + SM_S0);
    float* Msum = (float*)(smem + SM_MSUM);
    const uint32_t sb = smem_u32(smem);

    const int tid = threadIdx.x, wid = tid >> 5, lane = tid & 31;
    const int node = blockIdx.y;
    const int b0 = blockIdx.x * 32;

    const float* yin = (insel == 0) ? g_buf0 : g_buf1;
    float* yout = (outsel == 0) ? g_buf0 : ((outsel == 1) ? g_buf1 : dout);

    cp_wtile(sb + SM_W0, g_wh + (size_t)(wlo + 2 * node) * (KK * KK), tid);
    cp_wtile(sb + SM_W1, g_wh + (size_t)(wlo + 2 * node + 1) * (KK * KK), tid);

    float4 v1r[4];
    float m0r[4], m1r[4];
    #pragma unroll
    for (int it = 0; it < 4; it++) {
        const int r = it * 8 + wid;
        const float* yg = yin + ((size_t)(4 * node) * BATCH + b0 + r) * KK;
        float4 a = ((const float4*)yg)[lane];
        float4 b = ((const float4*)(yg + BK))[lane];
        float4 c = ((const float4*)(yg + 2 * BK))[lane];
        float4 d = ((const float4*)(yg + 3 * BK))[lane];
        float4 v0, v1;
        v0.x = a.x + b.x; v0.y = a.y + b.y; v0.z = a.z + b.z; v0.w = a.w + b.w;
        v1.x = c.x + d.x; v1.y = c.y + d.y; v1.z = c.z + d.z; v1.w = c.w + d.w;
        float m0 = warp_max(max4(v0));
        float m1 = warp_max(max4(v1));
        build_A_row(As, r, lane, v0, m0);
        v1r[it] = v1; m0r[it] = m0; m1r[it] = m1;
    }

    AccFrag acc1[2], acc2[2];

    cp_wait<1>();
    __syncthreads();
    gemm32_acc(As, (const __half*)(smem + SM_W0), acc1, wid);
    __syncthreads();

    cp_wtile(sb + SM_W0, g_wh + (size_t)(wup + node) * (KK * KK), tid);

    #pragma unroll
    for (int it = 0; it < 4; it++)
        build_A_row(As, it * 8 + wid, lane, v1r[it], m1r[it]);

    cp_wait<1>();
    __syncthreads();
    gemm32_acc(As, (const __half*)(smem + SM_W1), acc2, wid);

    #pragma unroll
    for (int j = 0; j < 2; j++)
        #pragma unroll
        for (int e = 0; e < acc2[j].num_elements; e++)
            acc2[j].x[e] *= acc1[j].x[e];
    store_acc32(acc2, S0, wid);
    __syncthreads();

    #pragma unroll
    for (int it = 0; it < 4; it++) {
        const int r = it * 8 + wid;
        float4 p = *(const float4*)&S0[r * LDS + 4 * lane];
        float pmax = fmaxf(warp_max(max4(p)), 1e-35f);
        float inv = __fdividef(1.0f, pmax);
        __half2 h0 = __floats2half2_rn(p.x * inv, p.y * inv);
        __half2 h1 = __floats2half2_rn(p.z * inv, p.w * inv);
        uint2 pk; pk.x = *(uint32_t*)&h0; pk.y = *(uint32_t*)&h1;
        *(uint2*)&As[r * LDA + 4 * lane] = pk;
        if (lane == 0) Msum[r] = m0r[it] + m1r[it] + __logf(pmax);
    }

    cp_wait<0>();
    __syncthreads();
    gemm32_acc(As, (const __half*)(smem + SM_W0), acc2, wid);
    store_acc32(acc2, S0, wid);
    __syncthreads();

    {
        const int r = tid >> 3, c0 = (tid & 7) * 16;
        const float mrow = Msum[r];
        float* orow = yout + ((size_t)node * BATCH + b0 + r) * KK + c0;
        #pragma unroll
        for (int c = 0; c < 4; c++) {
            float4 s = *(const float4*)&S0[r * LDS + c0 + 4 * c];
            float4 o;
            o.x = mrow + __logf(s.x); o.y = mrow + __logf(s.y);
            o.z = mrow + __logf(s.z); o.w = mrow + __logf(s.w);
            ((float4*)orow)[c] = o;
        }
    }
}

extern "C" void kernel_launch(void* const* d_in, const int* in_sizes, int n_in,
                              void* d_out, int out_size) {
    const float* x  = (const float*)d_in[0];
    const float* mu = (const float*)d_in[1];
    const float* ls = (const float*)d_in[2];
    const float* w  = (const float*)d_in[3];
    float* out = (float*)d_out;

    cudaFuncSetAttribute(pair64_kernel<true>,  cudaFuncAttributeMaxDynamicSharedMemorySize, P64_BYTES);
    cudaFuncSetAttribute(pair64_kernel<false>, cudaFuncAttributeMaxDynamicSharedMemorySize, P64_BYTES);
    cudaFuncSetAttribute(pair_kernel, cudaFuncAttributeMaxDynamicSharedMemorySize, SMEM_BYTES);

    softmax_w_kernel<<<1023, 256>>>(w);

    // pairs: (leaf512+256) (128+64) -> 64-row blocks; (32+16)(8+4)(2+1) -> R7 32-row
    pair64_kernel<true ><<<dim3(4, 256), 256, P64_BYTES>>>(-1, 0, 0,   512, x, mu, ls, out); // -> buf0 (256)
    pair64_kernel<false><<<dim3(4, 64),  256, P64_BYTES>>>( 0, 1, 768, 896, x, mu, ls, out); // -> buf1 (64)
    pair_kernel<<<dim3(8, 16), 256, SMEM_BYTES>>>( 1, 0, 960,  992,  out);                   // -> buf0 (16)
    pair_kernel<<<dim3(8, 4),  256, SMEM_BYTES>>>( 0, 1, 1008, 1016, out);                   // -> buf1 (4)
    pair_kernel<<<dim3(8, 1),  256, SMEM_BYTES>>>( 1, 2, 1020, 1022, out);                   // -> out (root)
}